// round 6
// baseline (speedup 1.0000x reference)
#include <cuda_runtime.h>
#include <cuda_bf16.h>
#include <cstdint>

// Problem dimensions (fixed by setup_inputs)
#define BB 9600      // batch rows (Z)
#define SS 2400      // candidate rows (Y)
#define SPAD 2432    // S padded to multiple of 128
#define FF 4096      // feature dim
#define NCH (FF / 32)  // 32-elem K chunks for GEMM

// ---------------------------------------------------------------------------
// Scratch (device globals: allocation-free rule). 2-way bf16 split.
__device__ __nv_bfloat16 g_Zh[(size_t)BB * FF];
__device__ __nv_bfloat16 g_Zm[(size_t)BB * FF];
__device__ __nv_bfloat16 g_Yh[(size_t)SPAD * FF];
__device__ __nv_bfloat16 g_Ym[(size_t)SPAD * FF];
__device__ float g_Znorm[BB];
__device__ float g_Ynorm[SS];
__device__ float g_simL[BB];
__device__ int   g_labels[BB];
__device__ int   g_inv[SS];
__device__ int   g_gt[BB];
__device__ int   g_eqb[BB];
__device__ int   g_hit[2];

// ---------------------------------------------------------------------------
// Launch 1: zero counters + scatter inverse map (test values unique per spec,
// and cover [0,SS) -> plain store is deterministic, no init ordering needed).
__global__ void init_scatter_kernel(const int* __restrict__ test) {
    int i = blockIdx.x * blockDim.x + threadIdx.x;
    if (i < BB) { g_gt[i] = 0; g_eqb[i] = 0; }
    if (i < 2)  g_hit[i] = 0;
    if (i < SS) {
        int v = test[i];
        if (v >= 0 && v < SS) g_inv[v] = i;
    }
}

__device__ __forceinline__ uint32_t pack_bf2(__nv_bfloat16 a, __nv_bfloat16 b) {
    __nv_bfloat162 t = __halves2bfloat162(a, b);
    return *reinterpret_cast<uint32_t*>(&t);
}

// Launch 2: normalize row, split into 2 bf16 components (h, m). Covers Z and Y.
__global__ void norm_split_kernel(const float* __restrict__ Zsrc,
                                  const float* __restrict__ Ysrc) {
    int row = blockIdx.x;
    int tid = threadIdx.x;  // 128 threads
    const float* src;
    __nv_bfloat16 *H, *M;
    int which;
    if (row < BB) {
        src = Zsrc; H = g_Zh; M = g_Zm; which = 0;
    } else {
        row -= BB;
        src = Ysrc; H = g_Yh; M = g_Ym; which = 1;
    }
    size_t base = (size_t)row * FF;

    if (which == 1 && row >= SS) {  // zero padding rows (Y only)
        for (int j = 0; j < 8; j++) {
            size_t off = base + tid * 4 + j * 512;
            *(uint2*)(H + off) = make_uint2(0, 0);
            *(uint2*)(M + off) = make_uint2(0, 0);
        }
        return;
    }

    float4 v[8];
    float s = 0.f;
#pragma unroll
    for (int j = 0; j < 8; j++) {
        v[j] = *(const float4*)(src + base + tid * 4 + j * 512);
        s += v[j].x * v[j].x + v[j].y * v[j].y + v[j].z * v[j].z + v[j].w * v[j].w;
    }
    for (int o = 16; o > 0; o >>= 1) s += __shfl_xor_sync(0xffffffffu, s, o);
    __shared__ float red[4];
    __shared__ float s_n;
    if ((tid & 31) == 0) red[tid >> 5] = s;
    __syncthreads();
    if (tid == 0) {
        float t = red[0] + red[1] + red[2] + red[3];
        s_n = fmaxf(sqrtf(t), 1e-8f);
        if (which == 0) g_Znorm[row] = s_n;
        else            g_Ynorm[row] = s_n;
    }
    __syncthreads();
    float n = s_n;

#pragma unroll
    for (int j = 0; j < 8; j++) {
        size_t off = base + tid * 4 + j * 512;
        float x[4] = {v[j].x / n, v[j].y / n, v[j].z / n, v[j].w / n};
        __nv_bfloat16 h[4], m[4];
#pragma unroll
        for (int e = 0; e < 4; e++) {
            h[e] = __float2bfloat16(x[e]);
            float r1 = x[e] - __bfloat162float(h[e]);
            m[e] = __float2bfloat16(r1);
        }
        *(uint2*)(H + off) = make_uint2(pack_bf2(h[0], h[1]), pack_bf2(h[2], h[3]));
        *(uint2*)(M + off) = make_uint2(pack_bf2(m[0], m[1]), pack_bf2(m[2], m[3]));
    }
}

// Launch 3: labels[i] = inv[yidx[i]]; simL[i] = cos-sim(Z[i], Y[lab]) in fp32.
__global__ void labels_simL_kernel(const float* __restrict__ Z,
                                   const float* __restrict__ Y,
                                   const int* __restrict__ yidx) {
    int i = blockIdx.x;
    int tid = threadIdx.x;  // 128
    __shared__ int s_lab;
    if (tid == 0) {
        int v = yidx[i];
        int lab = 0;
        if (v >= 0 && v < SS) lab = g_inv[v];
        g_labels[i] = lab;
        s_lab = lab;
    }
    __syncthreads();
    int lab = s_lab;
    const float* z = Z + (size_t)i * FF;
    const float* y = Y + (size_t)lab * FF;
    float s = 0.f;
    for (int c = tid * 4; c < FF; c += 512) {
        float4 a = *(const float4*)(z + c);
        float4 b = *(const float4*)(y + c);
        s += a.x * b.x + a.y * b.y + a.z * b.z + a.w * b.w;
    }
    for (int o = 16; o > 0; o >>= 1) s += __shfl_xor_sync(0xffffffffu, s, o);
    __shared__ float red[4];
    if ((tid & 31) == 0) red[tid >> 5] = s;
    __syncthreads();
    if (tid == 0) {
        float t = red[0] + red[1] + red[2] + red[3];
        g_simL[i] = t / (g_Znorm[i] * g_Ynorm[lab]);
    }
}

// ---------------------------------------------------------------------------
// Launch 4: fused bf16 HMMA GEMM (Ah*Bh + Ah*Bm + Am*Bh, fp32 accum) +
// rank-count epilogue. 128x128 tile, BK=32, 3-stage cp.async pipeline,
// 4 warps / 64x64 warp tiles, intra-chunk ldmatrix double-buffering.
#define TILE_B  8192                 // 128 rows x 32 bf16 (64B)
#define STAGE_B (4 * TILE_B)         // Ah Am Bh Bm per stage (32 KB)
#define NSTAGE 3
#define SMEM_DYN (NSTAGE * STAGE_B)  // 96 KB

__device__ __forceinline__ uint32_t swz(int r, int c) {
    return (uint32_t)(r * 64 + ((c ^ ((r >> 1) & 3)) << 4));
}

static __device__ __forceinline__ uint32_t cvta_s(const void* p) {
    uint32_t a;
    asm("{ .reg .u64 t; cvta.to.shared.u64 t, %1; cvt.u32.u64 %0, t; }" : "=r"(a) : "l"(p));
    return a;
}

__device__ __forceinline__ void ldsm_x4(uint32_t* r, uint32_t addr) {
    asm volatile("ldmatrix.sync.aligned.m8n8.x4.shared.b16 {%0,%1,%2,%3}, [%4];"
                 : "=r"(r[0]), "=r"(r[1]), "=r"(r[2]), "=r"(r[3]) : "r"(addr));
}

__device__ __forceinline__ void mma16816(float* c, const uint32_t* a, uint32_t b0, uint32_t b1) {
    asm volatile(
        "mma.sync.aligned.m16n8k16.row.col.f32.bf16.bf16.f32 "
        "{%0,%1,%2,%3}, {%4,%5,%6,%7}, {%8,%9}, {%0,%1,%2,%3};"
        : "+f"(c[0]), "+f"(c[1]), "+f"(c[2]), "+f"(c[3])
        : "r"(a[0]), "r"(a[1]), "r"(a[2]), "r"(a[3]), "r"(b0), "r"(b1));
}

extern __shared__ char dsm[];

__device__ __forceinline__ void fill_chunk(uint32_t stagebase, int c, int tid,
                                           const __nv_bfloat16* const* srcs) {
#pragma unroll
    for (int t = 0; t < 4; t++) {
        const __nv_bfloat16* sb = srcs[t] + c * 32;
#pragma unroll
        for (int j = 0; j < 4; j++) {
            int idx = tid + j * 128;        // 512 16B ops per tile, 128 threads
            int r = idx >> 2, ck = idx & 3;
            const void* src = sb + (size_t)r * FF + ck * 8;
            uint32_t dst = stagebase + t * TILE_B + swz(r, ck);
            asm volatile("cp.async.cg.shared.global [%0], [%1], 16;" :: "r"(dst), "l"(src));
        }
    }
    asm volatile("cp.async.commit_group;" ::: "memory");
}

__global__ __launch_bounds__(128, 2) void gemm_count_kernel() {
    int tid = threadIdx.x;
    int lane = tid & 31, wid = tid >> 5;
    int warp_m = wid & 1;          // 2 warps along M, 64 rows each
    int warp_n = wid >> 1;         // 2 warps along N, 64 cols each
    int brow = blockIdx.y * 128;
    int bcol = blockIdx.x * 128;
    uint32_t smem = cvta_s(dsm);

    const __nv_bfloat16* srcs[4] = {
        g_Zh + (size_t)brow * FF, g_Zm + (size_t)brow * FF,
        g_Yh + (size_t)bcol * FF, g_Ym + (size_t)bcol * FF};

    float acc[4][8][4];
#pragma unroll
    for (int i = 0; i < 4; i++)
#pragma unroll
        for (int j = 0; j < 8; j++)
#pragma unroll
            for (int v = 0; v < 4; v++) acc[i][j][v] = 0.f;

    fill_chunk(smem + 0 * STAGE_B, 0, tid, srcs);
    fill_chunk(smem + 1 * STAGE_B, 1, tid, srcs);

    // Per-lane ldmatrix row/chunk components
    int a_r = warp_m * 64 + (lane & 15);        // + i*16
    int b_r = warp_n * 64 + (lane & 15);        // + g*16
    int csel = lane >> 4;                        // 16B chunk within k16: +ks*2

    // slot s (0..5): product p = s/2 (Ah*Bh, Ah*Bm, Am*Bh), k-half ks = s&1
    // tile offsets within stage: A from {0:Ah,1:Am}, B from {2:Bh,3:Bm}
    const int sA[6] = {0, 0, 0, 0, 1, 1};
    const int sB[6] = {2, 2, 3, 3, 2, 2};

    uint32_t fa[2][4][4], fb[2][4][4];  // double-buffered fragments

    int stage = 0;
    for (int c = 0; c < NCH; c++) {
        uint32_t buf = smem + stage * STAGE_B;
        if (c < NCH - 2) asm volatile("cp.async.wait_group 1;" ::: "memory");
        else             asm volatile("cp.async.wait_group 0;" ::: "memory");
        __syncthreads();

        if (c + 2 < NCH) {
            int ns = stage + 2; if (ns >= NSTAGE) ns -= NSTAGE;
            fill_chunk(smem + ns * STAGE_B, c + 2, tid, srcs);
        }

        // preload slot 0 fragments
        {
            uint32_t tA = buf + sA[0] * TILE_B, tB = buf + sB[0] * TILE_B;
            int ks = 0;
#pragma unroll
            for (int i = 0; i < 4; i++) ldsm_x4(fa[0][i], tA + swz(a_r + i * 16, ks * 2 + csel));
#pragma unroll
            for (int g = 0; g < 4; g++) ldsm_x4(fb[0][g], tB + swz(b_r + g * 16, ks * 2 + csel));
        }

#pragma unroll
        for (int s = 0; s < 6; s++) {
            int cur = s & 1, nxt = cur ^ 1;
            if (s < 5) {  // prefetch slot s+1 while slot s MMAs run
                uint32_t tA = buf + sA[s + 1] * TILE_B, tB = buf + sB[s + 1] * TILE_B;
                int ks = (s + 1) & 1;
#pragma unroll
                for (int i = 0; i < 4; i++)
                    ldsm_x4(fa[nxt][i], tA + swz(a_r + i * 16, ks * 2 + csel));
#pragma unroll
                for (int g = 0; g < 4; g++)
                    ldsm_x4(fb[nxt][g], tB + swz(b_r + g * 16, ks * 2 + csel));
            }
#pragma unroll
            for (int i = 0; i < 4; i++)
#pragma unroll
                for (int jj = 0; jj < 8; jj++) {
                    int g = jj >> 1, w = jj & 1;
                    mma16816(acc[i][jj], fa[cur][i], fb[cur][g][w], fb[cur][g][2 + w]);
                }
        }
        stage++; if (stage >= NSTAGE) stage -= NSTAGE;
    }

    // Epilogue: rank counting. acc[i][jj][v]: row = warp_m*64+i*16+(lane>>2)+8*(v>>1),
    // col = warp_n*64 + jj*8 + (lane&3)*2 + (v&1)
#pragma unroll
    for (int i = 0; i < 4; i++) {
#pragma unroll
        for (int h = 0; h < 2; h++) {
            int row = brow + warp_m * 64 + i * 16 + (lane >> 2) + h * 8;
            float sl = g_simL[row];
            int lab = g_labels[row];
            int gt = 0, eqb = 0;
#pragma unroll
            for (int jj = 0; jj < 8; jj++) {
#pragma unroll
                for (int w = 0; w < 2; w++) {
                    int col = bcol + warp_n * 64 + jj * 8 + (lane & 3) * 2 + w;
                    float v = acc[i][jj][h * 2 + w];
                    if (col < SS && col != lab) {
                        if (v > sl) gt++;
                        else if (v == sl && col < lab) eqb++;
                    }
                }
            }
            gt  += __shfl_xor_sync(0xffffffffu, gt, 1);
            gt  += __shfl_xor_sync(0xffffffffu, gt, 2);
            eqb += __shfl_xor_sync(0xffffffffu, eqb, 1);
            eqb += __shfl_xor_sync(0xffffffffu, eqb, 2);
            if ((lane & 3) == 0) {
                if (gt)  atomicAdd(&g_gt[row], gt);
                if (eqb) atomicAdd(&g_eqb[row], eqb);
            }
        }
    }
}

// ---------------------------------------------------------------------------
__global__ void finalize_kernel() {
    int i = blockIdx.x * blockDim.x + threadIdx.x;
    if (i >= BB) return;
    int r = g_gt[i] + g_eqb[i];
    if (r < 1) atomicAdd(&g_hit[0], 1);
    if (r < 5) atomicAdd(&g_hit[1], 1);
}

__global__ void writeout_kernel(float* __restrict__ out) {
    out[0] = (float)g_hit[0] / (float)BB;
    out[1] = (float)g_hit[1] / (float)BB;
}

// ---------------------------------------------------------------------------
extern "C" void kernel_launch(void* const* d_in, const int* in_sizes, int n_in,
                              void* d_out, int out_size) {
    (void)in_sizes; (void)n_in; (void)out_size;
    const float* Z    = (const float*)d_in[0];
    const int*   yidx = (const int*)d_in[1];
    const float* Y    = (const float*)d_in[2];
    const int*   test = (const int*)d_in[3];
    float* out = (float*)d_out;

    cudaFuncSetAttribute(gemm_count_kernel,
                         cudaFuncAttributeMaxDynamicSharedMemorySize, SMEM_DYN);

    init_scatter_kernel<<<(BB + 255) / 256, 256>>>(test);      // launch 1
    norm_split_kernel<<<BB + SPAD, 128>>>(Z, Y);               // launch 2
    labels_simL_kernel<<<BB, 128>>>(Z, Y, yidx);               // launch 3

    dim3 grid(SPAD / 128, BB / 128);
    gemm_count_kernel<<<grid, 128, SMEM_DYN>>>();              // launch 4 (ncu target)

    finalize_kernel<<<(BB + 255) / 256, 256>>>();              // launch 5
    writeout_kernel<<<1, 1>>>(out);                            // launch 6
}